// round 11
// baseline (speedup 1.0000x reference)
#include <cuda_runtime.h>

// XrayTransforms: standardize -> soft-hist equalize -> 2x bilinear (=2x2 avg) -> normalize
// x: (2,1,512,512) f32, out: (2,1,256,256) f32
//
// Round 11: persistent kernel v2. 128 blocks x 512 threads, 3 grid barriers.
//   A: zero g_mom slice; load 8 px -> REGISTERS; block minmax partials   [bar]
//   B: reduce minmax; bin the 8 register px (smem atomics); flush g_mom  [bar]
//   C: stage padded fine hist (36KB); conv ALL 256 bins redundantly
//      (16 warps x 16 bins, conflict-free); scan; 128 table entries      [bar]
//   E: 2 output px/thread via table lerp

#define NB 256
#define HW 512
#define NPIX (HW*HW)            // 262144 per batch
#define SUBN 8192
#define SUBSCALE 8160.0f        // 255*32 sub-bins across [0,1]
#define BETA 7.5091258e-5f      // A / 8160^2, A = 5000
#define STEP32_C 0.85745500f    // exp(-2048*BETA) = exp(-2*A*Delta^2)
#define TABN 8192
#define GRID 128
#define RADIUS 12
#define TWO_A_D  39.21568627450980f   // 2*A*Delta (Delta = 1/255)
#define A_D2     0.07689350249903883f // A*Delta^2
#define RATIO_C  0.85745500f          // exp(-2*A*Delta^2)
#define INV255   (1.0f/255.0f)
#define PWIN 9088               // 420 pad + 8192 + 444 pad (+ slack)

__device__ float g_pmin[GRID];
__device__ float g_pmax[GRID];
__device__ float g_mom[2][SUBN];
__device__ float g_eqtab[2][TABN];

__device__ volatile int g_bar_cnt;
__device__ volatile int g_bar_gen;

__device__ __forceinline__ void gridbar() {
    __syncthreads();
    if (threadIdx.x == 0) {
        int gen = g_bar_gen;
        __threadfence();
        if (atomicAdd((int*)&g_bar_cnt, 1) == GRID - 1) {
            g_bar_cnt = 0;
            __threadfence();
            atomicExch((int*)&g_bar_gen, gen + 1);
        } else {
            while (g_bar_gen == gen) __nanosleep(32);
            __threadfence();
        }
    }
    __syncthreads();
}

__device__ __forceinline__ float eq_lerp(float xraw, float mn, float inv,
                                         const float* __restrict__ tb) {
    float v = (xraw - mn) * inv;
    float t = v * (float)(TABN - 1);
    int i0 = (int)t;
    float f = t - (float)i0;
    float e0 = __ldg(tb + i0);
    float e1 = __ldg(tb + i0 + 1);
    return fmaf(f, e1 - e0, e0);
}

__global__ void __launch_bounds__(512, 1)
k_fused(const float* __restrict__ x, float* __restrict__ out) {
    __shared__ float P[PWIN];          // 36KB: bins (B) / padded conv window (C)
    __shared__ float W[1024];          // reduce scratch
    __shared__ float SC[NB];           // scan
    __shared__ float CP[NB + 2*RADIUS];
    __shared__ float MP[NB + 2*RADIUS];
    __shared__ float s_mn, s_inv;

    const int bid = blockIdx.x;
    const int t = threadIdx.x;
    const int b = bid >> 6;            // 64 blocks per batch
    const int sl = bid & 63;
    const float4* x4 = (const float4*)x;

    // ---- Phase A: zero g_mom slice, load 8 px to regs, block minmax ----
    if (t < 128) ((float*)g_mom)[bid * 128 + t] = 0.0f;
    float4 p0 = x4[b * (NPIX / 4) + sl * 1024 + t];
    float4 p1 = x4[b * (NPIX / 4) + sl * 1024 + 512 + t];
    {
        float mn = fminf(fminf(p0.x, p0.y), fminf(p0.z, p0.w));
        float mx = fmaxf(fmaxf(p0.x, p0.y), fmaxf(p0.z, p0.w));
        mn = fminf(mn, fminf(fminf(p1.x, p1.y), fminf(p1.z, p1.w)));
        mx = fmaxf(mx, fmaxf(fmaxf(p1.x, p1.y), fmaxf(p1.z, p1.w)));
        W[t] = mn; W[512 + t] = mx;
        __syncthreads();
        for (int o = 256; o; o >>= 1) {
            if (t < o) {
                W[t] = fminf(W[t], W[t + o]);
                W[512 + t] = fmaxf(W[512 + t], W[512 + t + o]);
            }
            __syncthreads();
        }
        if (t == 0) { g_pmin[bid] = W[0]; g_pmax[bid] = W[512]; }
    }
    gridbar();

    // ---- Phase B: reduce partials -> scale; bin register px; flush ----
    {
        W[t] = (t < GRID) ? g_pmin[t] : 1e30f;
        W[512 + t] = (t < GRID) ? g_pmax[t] : -1e30f;
        __syncthreads();
        for (int o = 256; o; o >>= 1) {
            if (t < o) {
                W[t] = fminf(W[t], W[t + o]);
                W[512 + t] = fmaxf(W[512 + t], W[512 + t + o]);
            }
            __syncthreads();
        }
        if (t == 0) { s_mn = W[0]; s_inv = 1.0f / (W[512] - W[0] + 1e-6f); }
    }
    for (int i = t; i < PWIN; i += 512) P[i] = 0.0f;
    __syncthreads();
    const float mn  = s_mn;
    const float inv = s_inv;
    {
        float vv[8] = {p0.x, p0.y, p0.z, p0.w, p1.x, p1.y, p1.z, p1.w};
        #pragma unroll
        for (int q = 0; q < 8; q++) {
            float v = (vv[q] - mn) * inv;
            int i = __float2int_rn(v * SUBSCALE);
            atomicAdd(&P[420 + i], 1.0f);
        }
        __syncthreads();
        float* dst = g_mom[b];
        for (int i = t; i < SUBN; i += 512) {
            float v = P[420 + i];
            if (v != 0.0f) atomicAdd(&dst[i], v);   // exact integer counts
        }
    }
    gridbar();

    // ---- Phase C: stage padded hist; conv all 256 bins; scan; table ----
    {
        for (int i = t; i < PWIN; i += 512) {
            int gi = i - 420;
            P[i] = (gi >= 0 && gi < SUBN) ? g_mom[b][gi] : 0.0f;
        }
        if (t < NB + 2 * RADIUS) { CP[t] = 0.0f; MP[t] = 0.0f; }
        __syncthreads();

        const int wid = t >> 5;        // 16 warps
        const int lane = t & 31;
        #pragma unroll
        for (int jj = 0; jj < 16; jj++) {
            const int j = wid * 16 + jj;                 // bin 0..255
            float fm = (float)(lane - 420);
            float w = __expf(-BETA * fm * fm);
            float r = __expf(-BETA * (64.0f * fm + 1024.0f));
            const float* p = P + 32 * j + lane;          // P[420 + 32j + m]
            float h = 0.0f;
            #pragma unroll
            for (int it = 0; it < 27; it++) {
                h += w * p[it * 32];
                w *= r;
                r *= STEP32_C;
            }
            #pragma unroll
            for (int o = 16; o; o >>= 1) h += __shfl_xor_sync(0xFFFFFFFFu, h, o);
            if (lane == 0) SC[j] = h;
        }
        __syncthreads();
        #pragma unroll
        for (int o = 1; o < NB; o <<= 1) {
            float add = (t < NB && t >= o) ? SC[t - o] : 0.0f;
            __syncthreads();
            if (t < NB) SC[t] += add;
            __syncthreads();
        }
        if (t < NB) {
            float total = SC[NB - 1];
            float invS  = 1.0f / (total + 1e-10f);
            float cdf   = SC[t] * invS;
            float cdf0  = SC[0] * invS;
            CP[t + RADIUS] = (cdf - cdf0) / (1.0f - cdf0 + 1e-10f);
            MP[t + RADIUS] = 1.0f;
        }
        __syncthreads();
        if (t < 128) {
            int p = sl * 128 + t;                        // 0..8191
            float v = (float)p * (1.0f / (float)(TABN - 1));
            int k = __float2int_rn(v * 255.0f);
            int jlo = k - RADIUS;
            float d0 = v - (float)jlo * INV255;
            float w = __expf(-5000.0f * d0 * d0);
            float r = __expf(TWO_A_D * d0 - A_D2);
            const float* cpp = CP + jlo + RADIUS;
            const float* mpp = MP + jlo + RADIUS;
            float num = 0.0f, den = 0.0f;
            #pragma unroll
            for (int st = 0; st < 2 * RADIUS + 1; st++) {
                num = fmaf(w, cpp[st], num);
                den = fmaf(w, mpp[st], den);
                w *= r;
                r *= RATIO_C;
            }
            g_eqtab[b][p] = num / (den + 1e-10f);
        }
    }
    gridbar();

    // ---- Phase E: 1024 output px per block ----
    #pragma unroll
    for (int q = 0; q < 2; q++) {
        int idx = bid * 1024 + q * 512 + t;              // 131072 output px
        int b2 = idx >> 16;
        int rem = idx & 0xFFFF;
        int oy = rem >> 8;
        int ox = rem & 255;
        const float* base = x + b2 * NPIX;
        float2 t0 = ((const float2*)(base + (2 * oy)     * HW))[ox];
        float2 t1 = ((const float2*)(base + (2 * oy + 1) * HW))[ox];
        const float* tb = g_eqtab[b2];
        float e = eq_lerp(t0.x, mn, inv, tb)
                + eq_lerp(t0.y, mn, inv, tb)
                + eq_lerp(t1.x, mn, inv, tb)
                + eq_lerp(t1.y, mn, inv, tb);
        out[idx] = (0.25f * e - 0.15f) / 0.1f;
    }
}

extern "C" void kernel_launch(void* const* d_in, const int* in_sizes, int n_in,
                              void* d_out, int out_size) {
    const float* x = (const float*)d_in[0];
    float* out = (float*)d_out;
    k_fused<<<GRID, 512>>>(x, out);
}

// round 12
// speedup vs baseline: 1.4443x; 1.4443x over previous
#include <cuda_runtime.h>

// XrayTransforms: standardize -> soft-hist equalize -> 2x bilinear (=2x2 avg) -> normalize
// x: (2,1,512,512) f32, out: (2,1,256,256) f32
//
// Round 12: 4 kernels, SUBN=2048 (8 sub-bins per bin).
//   k_minmax    : block min/max partials + zero g_mom
//   k_hist      : fine hist in smem (8KB), atomic flush to g_mom
//   k_convtable : stage padded fine hist; conv all 256 bins (7 taps/lane);
//                 scan -> cdfn; 512 eq-table entries per block
//   k_out       : 2x2 avg of table lerps + normalize

#define NB 256
#define HW 512
#define NPIX (HW*HW)            // 262144 per batch
#define SUBN 2048
#define SUBSCALE 2040.0f        // 255*8 sub-bins across [0,1]
#define BETA 1.2014610918e-3f   // A / 2040^2, A = 5000
#define RSTEP 0.08539095f       // exp(-2048*BETA): step-32 ratio multiplier
#define TABN 8192
#define NMM 128                 // minmax blocks
#define RADIUS 12
#define TWO_A_D  39.21568627450980f   // 2*A*Delta (Delta = 1/255)
#define A_D2     0.07689350249903883f // A*Delta^2
#define RATIO_C  0.85745500f          // exp(-2*A*Delta^2)
#define INV255   (1.0f/255.0f)
#define LPAD 112                // left pad (need 105)
#define PWIN 2304               // 112 + 2048 + 144 (right need 2158-2047=111... covered)
#define PAD (NB + 2*RADIUS)     // 280

__device__ float g_pmin[NMM];
__device__ float g_pmax[NMM];
__device__ float g_scale[2];            // [0]=min, [1]=1/(max-min+1e-6)
__device__ float g_mom[2][SUBN];        // fine hist (atomic-accumulated)
__device__ float g_eqtab[2][TABN];

__global__ void k_minmax(const float* __restrict__ x) {
    __shared__ float smn[256], smx[256];
    // zero g_mom: 128 blocks x 32 elements
    if (threadIdx.x < 32)
        ((float*)g_mom)[blockIdx.x * 32 + threadIdx.x] = 0.0f;

    const float4* x4 = (const float4*)x;
    int base = blockIdx.x * 1024 + threadIdx.x;     // 131072 float4 / 128 blocks
    float mn = 1e30f, mx = -1e30f;
    #pragma unroll
    for (int q = 0; q < 4; q++) {
        float4 v = x4[base + q * 256];
        mn = fminf(mn, fminf(fminf(v.x, v.y), fminf(v.z, v.w)));
        mx = fmaxf(mx, fmaxf(fmaxf(v.x, v.y), fmaxf(v.z, v.w)));
    }
    smn[threadIdx.x] = mn; smx[threadIdx.x] = mx;
    __syncthreads();
    for (int o = 128; o; o >>= 1) {
        if (threadIdx.x < o) {
            smn[threadIdx.x] = fminf(smn[threadIdx.x], smn[threadIdx.x + o]);
            smx[threadIdx.x] = fmaxf(smx[threadIdx.x], smx[threadIdx.x + o]);
        }
        __syncthreads();
    }
    if (threadIdx.x == 0) { g_pmin[blockIdx.x] = smn[0]; g_pmax[blockIdx.x] = smx[0]; }
}

// grid (64,2) x 512: 8 px/thread; 1 smem atomic per px; atomic flush to g_mom.
__global__ void k_hist(const float* __restrict__ x) {
    __shared__ float sh[SUBN];                 // 8KB
    __shared__ float smm[128];
    const int t = threadIdx.x;
    if (t < 128) smm[t] = g_pmin[t];
    __syncthreads();
    for (int o = 64; o; o >>= 1) { if (t < o) smm[t] = fminf(smm[t], smm[t + o]); __syncthreads(); }
    const float mn = smm[0];
    __syncthreads();
    if (t < 128) smm[t] = g_pmax[t];
    __syncthreads();
    for (int o = 64; o; o >>= 1) { if (t < o) smm[t] = fmaxf(smm[t], smm[t + o]); __syncthreads(); }
    const float inv = 1.0f / (smm[0] - mn + 1e-6f);
    if (blockIdx.x == 0 && blockIdx.y == 0 && t == 0) { g_scale[0] = mn; g_scale[1] = inv; }

    for (int i = t; i < SUBN; i += 512) sh[i] = 0.0f;
    __syncthreads();

    const int b = blockIdx.y;
    const float4* xb = (const float4*)(x + b * NPIX) + blockIdx.x * 1024;
    #pragma unroll
    for (int q = 0; q < 2; q++) {
        float4 p4 = xb[q * 512 + t];
        float vv[4] = {p4.x, p4.y, p4.z, p4.w};
        #pragma unroll
        for (int qq = 0; qq < 4; qq++) {
            float v = (vv[qq] - mn) * inv;
            int i = __float2int_rn(v * SUBSCALE);
            atomicAdd(&sh[i], 1.0f);
        }
    }
    __syncthreads();
    // counts are exact integers in f32 -> order-independent, deterministic
    float* dst = g_mom[b];
    for (int i = t; i < SUBN; i += 512) {
        float v = sh[i];
        if (v != 0.0f) atomicAdd(&dst[i], v);
    }
}

// grid (16,2) x 512: stage padded fine hist, conv all 256 bins (redundant per
// block, 7 taps/lane), scan -> padded cdfn, 512 table entries per block.
__global__ void k_convtable() {
    __shared__ float win[PWIN];
    __shared__ float SC[NB];
    __shared__ float CP[PAD];
    __shared__ float MP[PAD];
    const int b = blockIdx.y;
    const int t = threadIdx.x;          // 512 threads = 16 warps
    const int wid = t >> 5;
    const int lane = t & 31;

    for (int i = t; i < PWIN; i += 512) {
        int gi = i - LPAD;
        win[i] = (gi >= 0 && gi < SUBN) ? g_mom[b][gi] : 0.0f;
    }
    if (t < PAD) { CP[t] = 0.0f; MP[t] = 0.0f; }
    __syncthreads();

    // conv: warp per bin, lane taps m = -105+lane, step 32, 7 taps
    #pragma unroll
    for (int jj = 0; jj < 16; jj++) {
        const int j = wid * 16 + jj;                 // bin 0..255
        float fm = (float)(lane - 105);
        float w = __expf(-BETA * fm * fm);
        float r = __expf(-BETA * (64.0f * fm + 1024.0f));
        const float* p = win + LPAD + 8 * j + (lane - 105);
        float h = 0.0f;
        #pragma unroll
        for (int it = 0; it < 7; it++) {
            h += w * p[it * 32];
            w *= r;
            r *= RSTEP;
        }
        #pragma unroll
        for (int o = 16; o; o >>= 1) h += __shfl_xor_sync(0xFFFFFFFFu, h, o);
        if (lane == 0) SC[j] = h;
    }
    __syncthreads();

    #pragma unroll
    for (int o = 1; o < NB; o <<= 1) {
        float add = (t < NB && t >= o) ? SC[t - o] : 0.0f;
        __syncthreads();
        if (t < NB) SC[t] += add;
        __syncthreads();
    }
    if (t < NB) {
        float total = SC[NB - 1];
        float invS  = 1.0f / (total + 1e-10f);
        float cdf   = SC[t] * invS;
        float cdf0  = SC[0] * invS;
        CP[t + RADIUS] = (cdf - cdf0) / (1.0f - cdf0 + 1e-10f);
        MP[t + RADIUS] = 1.0f;
    }
    __syncthreads();

    int p = blockIdx.x * 512 + t;       // 0..TABN-1
    float v = (float)p * (1.0f / (float)(TABN - 1));
    int k = __float2int_rn(v * 255.0f);
    int jlo = k - RADIUS;
    float d0 = v - (float)jlo * INV255;
    float w = __expf(-5000.0f * d0 * d0);
    float r = __expf(TWO_A_D * d0 - A_D2);
    const float* cpp = CP + jlo + RADIUS;
    const float* mpp = MP + jlo + RADIUS;
    float num = 0.0f, den = 0.0f;
    #pragma unroll
    for (int st = 0; st < 2 * RADIUS + 1; st++) {
        num = fmaf(w, cpp[st], num);
        den = fmaf(w, mpp[st], den);
        w *= r;
        r *= RATIO_C;
    }
    g_eqtab[b][p] = num / (den + 1e-10f);
}

__device__ __forceinline__ float eq_lerp(float xraw, float mn, float inv,
                                         const float* __restrict__ tb) {
    float v = (xraw - mn) * inv;
    float t = v * (float)(TABN - 1);
    int i0 = (int)t;
    float f = t - (float)i0;
    float e0 = __ldg(tb + i0);
    float e1 = __ldg(tb + i0 + 1);
    return fmaf(f, e1 - e0, e0);
}

__global__ void k_out(const float* __restrict__ x, float* __restrict__ out) {
    int idx = blockIdx.x * blockDim.x + threadIdx.x;   // 131072 output pixels
    int b = idx >> 16;
    int rem = idx & 0xFFFF;
    int oy = rem >> 8;
    int ox = rem & 255;
    const float* base = x + b * NPIX;
    float2 t0 = ((const float2*)(base + (2 * oy)     * HW))[ox];
    float2 t1 = ((const float2*)(base + (2 * oy + 1) * HW))[ox];

    const float mn  = g_scale[0];
    const float inv = g_scale[1];
    const float* tb = g_eqtab[b];
    float e = eq_lerp(t0.x, mn, inv, tb)
            + eq_lerp(t0.y, mn, inv, tb)
            + eq_lerp(t1.x, mn, inv, tb)
            + eq_lerp(t1.y, mn, inv, tb);
    out[idx] = (0.25f * e - 0.15f) / 0.1f;
}

extern "C" void kernel_launch(void* const* d_in, const int* in_sizes, int n_in,
                              void* d_out, int out_size) {
    const float* x = (const float*)d_in[0];
    float* out = (float*)d_out;
    k_minmax<<<NMM, 256>>>(x);
    k_hist<<<dim3(64, 2), 512>>>(x);
    k_convtable<<<dim3(16, 2), 512>>>();
    k_out<<<512, 256>>>(x, out);
}

// round 13
// speedup vs baseline: 1.5945x; 1.1040x over previous
#include <cuda_runtime.h>

// XrayTransforms: standardize -> soft-hist equalize -> 2x bilinear (=2x2 avg) -> normalize
// x: (2,1,512,512) f32, out: (2,1,256,256) f32
//
// Round 13: k_out restaged — 128 blocks x 512 threads, eq-table in smem
// (32.8KB incl. +1 guard entry), 2 output px/thread via float4 input loads.
// Rest identical to round 12 (20.4us).

#define NB 256
#define HW 512
#define NPIX (HW*HW)            // 262144 per batch
#define SUBN 2048
#define SUBSCALE 2040.0f        // 255*8 sub-bins across [0,1]
#define BETA 1.2014610918e-3f   // A / 2040^2, A = 5000
#define RSTEP 0.08539095f       // exp(-2048*BETA): step-32 ratio multiplier
#define TABN 8192
#define NMM 128                 // minmax blocks
#define RADIUS 12
#define TWO_A_D  39.21568627450980f   // 2*A*Delta (Delta = 1/255)
#define A_D2     0.07689350249903883f // A*Delta^2
#define RATIO_C  0.85745500f          // exp(-2*A*Delta^2)
#define INV255   (1.0f/255.0f)
#define LPAD 112                // left pad (need 105)
#define PWIN 2304               // 112 + 2048 + 144
#define PAD (NB + 2*RADIUS)     // 280

__device__ float g_pmin[NMM];
__device__ float g_pmax[NMM];
__device__ float g_scale[2];            // [0]=min, [1]=1/(max-min+1e-6)
__device__ float g_mom[2][SUBN];        // fine hist (atomic-accumulated)
__device__ float g_eqtab[2][TABN];

__global__ void k_minmax(const float* __restrict__ x) {
    __shared__ float smn[256], smx[256];
    // zero g_mom: 128 blocks x 32 elements
    if (threadIdx.x < 32)
        ((float*)g_mom)[blockIdx.x * 32 + threadIdx.x] = 0.0f;

    const float4* x4 = (const float4*)x;
    int base = blockIdx.x * 1024 + threadIdx.x;     // 131072 float4 / 128 blocks
    float mn = 1e30f, mx = -1e30f;
    #pragma unroll
    for (int q = 0; q < 4; q++) {
        float4 v = x4[base + q * 256];
        mn = fminf(mn, fminf(fminf(v.x, v.y), fminf(v.z, v.w)));
        mx = fmaxf(mx, fmaxf(fmaxf(v.x, v.y), fmaxf(v.z, v.w)));
    }
    smn[threadIdx.x] = mn; smx[threadIdx.x] = mx;
    __syncthreads();
    for (int o = 128; o; o >>= 1) {
        if (threadIdx.x < o) {
            smn[threadIdx.x] = fminf(smn[threadIdx.x], smn[threadIdx.x + o]);
            smx[threadIdx.x] = fmaxf(smx[threadIdx.x], smx[threadIdx.x + o]);
        }
        __syncthreads();
    }
    if (threadIdx.x == 0) { g_pmin[blockIdx.x] = smn[0]; g_pmax[blockIdx.x] = smx[0]; }
}

// grid (64,2) x 512: 8 px/thread; 1 smem atomic per px; atomic flush to g_mom.
__global__ void k_hist(const float* __restrict__ x) {
    __shared__ float sh[SUBN];                 // 8KB
    __shared__ float smm[128];
    const int t = threadIdx.x;
    if (t < 128) smm[t] = g_pmin[t];
    __syncthreads();
    for (int o = 64; o; o >>= 1) { if (t < o) smm[t] = fminf(smm[t], smm[t + o]); __syncthreads(); }
    const float mn = smm[0];
    __syncthreads();
    if (t < 128) smm[t] = g_pmax[t];
    __syncthreads();
    for (int o = 64; o; o >>= 1) { if (t < o) smm[t] = fmaxf(smm[t], smm[t + o]); __syncthreads(); }
    const float inv = 1.0f / (smm[0] - mn + 1e-6f);
    if (blockIdx.x == 0 && blockIdx.y == 0 && t == 0) { g_scale[0] = mn; g_scale[1] = inv; }

    for (int i = t; i < SUBN; i += 512) sh[i] = 0.0f;
    __syncthreads();

    const int b = blockIdx.y;
    const float4* xb = (const float4*)(x + b * NPIX) + blockIdx.x * 1024;
    #pragma unroll
    for (int q = 0; q < 2; q++) {
        float4 p4 = xb[q * 512 + t];
        float vv[4] = {p4.x, p4.y, p4.z, p4.w};
        #pragma unroll
        for (int qq = 0; qq < 4; qq++) {
            float v = (vv[qq] - mn) * inv;
            int i = __float2int_rn(v * SUBSCALE);
            atomicAdd(&sh[i], 1.0f);
        }
    }
    __syncthreads();
    // counts are exact integers in f32 -> order-independent, deterministic
    float* dst = g_mom[b];
    for (int i = t; i < SUBN; i += 512) {
        float v = sh[i];
        if (v != 0.0f) atomicAdd(&dst[i], v);
    }
}

// grid (16,2) x 512: stage padded fine hist, conv all 256 bins (7 taps/lane),
// scan -> padded cdfn, 512 table entries per block.
__global__ void k_convtable() {
    __shared__ float win[PWIN];
    __shared__ float SC[NB];
    __shared__ float CP[PAD];
    __shared__ float MP[PAD];
    const int b = blockIdx.y;
    const int t = threadIdx.x;          // 512 threads = 16 warps
    const int wid = t >> 5;
    const int lane = t & 31;

    for (int i = t; i < PWIN; i += 512) {
        int gi = i - LPAD;
        win[i] = (gi >= 0 && gi < SUBN) ? g_mom[b][gi] : 0.0f;
    }
    if (t < PAD) { CP[t] = 0.0f; MP[t] = 0.0f; }
    __syncthreads();

    #pragma unroll
    for (int jj = 0; jj < 16; jj++) {
        const int j = wid * 16 + jj;                 // bin 0..255
        float fm = (float)(lane - 105);
        float w = __expf(-BETA * fm * fm);
        float r = __expf(-BETA * (64.0f * fm + 1024.0f));
        const float* p = win + LPAD + 8 * j + (lane - 105);
        float h = 0.0f;
        #pragma unroll
        for (int it = 0; it < 7; it++) {
            h += w * p[it * 32];
            w *= r;
            r *= RSTEP;
        }
        #pragma unroll
        for (int o = 16; o; o >>= 1) h += __shfl_xor_sync(0xFFFFFFFFu, h, o);
        if (lane == 0) SC[j] = h;
    }
    __syncthreads();

    #pragma unroll
    for (int o = 1; o < NB; o <<= 1) {
        float add = (t < NB && t >= o) ? SC[t - o] : 0.0f;
        __syncthreads();
        if (t < NB) SC[t] += add;
        __syncthreads();
    }
    if (t < NB) {
        float total = SC[NB - 1];
        float invS  = 1.0f / (total + 1e-10f);
        float cdf   = SC[t] * invS;
        float cdf0  = SC[0] * invS;
        CP[t + RADIUS] = (cdf - cdf0) / (1.0f - cdf0 + 1e-10f);
        MP[t + RADIUS] = 1.0f;
    }
    __syncthreads();

    int p = blockIdx.x * 512 + t;       // 0..TABN-1
    float v = (float)p * (1.0f / (float)(TABN - 1));
    int k = __float2int_rn(v * 255.0f);
    int jlo = k - RADIUS;
    float d0 = v - (float)jlo * INV255;
    float w = __expf(-5000.0f * d0 * d0);
    float r = __expf(TWO_A_D * d0 - A_D2);
    const float* cpp = CP + jlo + RADIUS;
    const float* mpp = MP + jlo + RADIUS;
    float num = 0.0f, den = 0.0f;
    #pragma unroll
    for (int st = 0; st < 2 * RADIUS + 1; st++) {
        num = fmaf(w, cpp[st], num);
        den = fmaf(w, mpp[st], den);
        w *= r;
        r *= RATIO_C;
    }
    g_eqtab[b][p] = num / (den + 1e-10f);
}

__device__ __forceinline__ float eq_lerp_s(float xraw, float mn, float inv,
                                           const float* __restrict__ tb) {
    float v = (xraw - mn) * inv;
    float t = v * (float)(TABN - 1);
    int i0 = (int)t;
    float f = t - (float)i0;
    float e0 = tb[i0];
    float e1 = tb[i0 + 1];
    return fmaf(f, e1 - e0, e0);
}

// 128 blocks x 512 threads; eq-table staged in smem (+1 guard); 2 out px/thread.
__global__ void __launch_bounds__(512)
k_out(const float* __restrict__ x, float* __restrict__ out) {
    __shared__ float tab[TABN + 1];     // 32.8KB
    const int t = threadIdx.x;
    const int b = blockIdx.x >> 6;      // 64 blocks per batch
    const int sl = blockIdx.x & 63;

    {
        const float4* src = (const float4*)g_eqtab[b];
        float4* dst4 = (float4*)tab;
        #pragma unroll
        for (int q = 0; q < 4; q++) dst4[q * 512 + t] = src[q * 512 + t];
        if (t == 0) tab[TABN] = tab[TABN - 1];   // guard for v == 1.0
    }
    __syncthreads();

    const float mn  = g_scale[0];
    const float inv = g_scale[1];

    // block covers 4 output rows (sl*4 .. sl*4+3); thread -> 2 adjacent out px
    int local = 2 * t;                   // 0..1022
    int oy = sl * 4 + (local >> 8);
    int ox = local & 255;                // even
    const float* base = x + b * NPIX;
    float4 r0 = *(const float4*)(base + (2 * oy)     * HW + 2 * ox);
    float4 r1 = *(const float4*)(base + (2 * oy + 1) * HW + 2 * ox);

    float e0 = eq_lerp_s(r0.x, mn, inv, tab) + eq_lerp_s(r0.y, mn, inv, tab)
             + eq_lerp_s(r1.x, mn, inv, tab) + eq_lerp_s(r1.y, mn, inv, tab);
    float e1 = eq_lerp_s(r0.z, mn, inv, tab) + eq_lerp_s(r0.w, mn, inv, tab)
             + eq_lerp_s(r1.z, mn, inv, tab) + eq_lerp_s(r1.w, mn, inv, tab);

    float2 o2;
    o2.x = (0.25f * e0 - 0.15f) / 0.1f;
    o2.y = (0.25f * e1 - 0.15f) / 0.1f;
    *(float2*)(out + b * 65536 + oy * 256 + ox) = o2;
}

extern "C" void kernel_launch(void* const* d_in, const int* in_sizes, int n_in,
                              void* d_out, int out_size) {
    const float* x = (const float*)d_in[0];
    float* out = (float*)d_out;
    k_minmax<<<NMM, 256>>>(x);
    k_hist<<<dim3(64, 2), 512>>>(x);
    k_convtable<<<dim3(16, 2), 512>>>();
    k_out<<<128, 512>>>(x, out);
}